// round 2
// baseline (speedup 1.0000x reference)
#include <cuda_runtime.h>
#include <math.h>

#define BB 64
#define TT 2048
#define HH 512
#define QQ 512
#define NCHUNK 16
#define CHUNK (TT / NCHUNK)   // 128 rows per chunk

// Scratch (allocation-free rule: __device__ globals)
__device__ __align__(16) float g_v[BB * HH];             // v[b] = W^T q[b]
__device__ float g_pm[BB * NCHUNK];                      // per-chunk running max
__device__ float g_ps[BB * NCHUNK];                      // per-chunk exp-sum
__device__ __align__(16) float g_pctx[BB * NCHUNK * HH]; // per-chunk weighted ctx (2 MB)

// ---------------------------------------------------------------------------
// tgt_index dtype detection: buffer is either 64 x int64 (odd int32 words all
// zero, values < 2048) or 64 x int32 (random in [0,2048): odd words ~never all
// zero). Reading the first 64 int32 words is in-bounds in both cases.
// ---------------------------------------------------------------------------
__device__ __forceinline__ int detect_is64(const int* __restrict__ tgt_raw) {
    int odd_or = 0;
#pragma unroll
    for (int i = 1; i < 2 * BB; i += 2) odd_or |= tgt_raw[i];
    return odd_or == 0;
}

__device__ __forceinline__ int load_len(const int* __restrict__ tgt_raw, int b, int is64) {
    return (is64 ? tgt_raw[2 * b] : tgt_raw[b]) + 1;
}

// ---------------------------------------------------------------------------
// Kernel 1: v[b,h] = sum_q query[b,q] * W[q,h]
// grid (H/128, B/4), 128 threads. W column-tile stays coalesced; query in smem.
// ---------------------------------------------------------------------------
#define K1_HTILE 128
#define K1_BGRP  4

__global__ void k1_proj(const float* __restrict__ query, const float* __restrict__ W) {
    __shared__ float sq[K1_BGRP][QQ];
    const int b0 = blockIdx.y * K1_BGRP;
    const int h  = blockIdx.x * K1_HTILE + threadIdx.x;

    for (int i = threadIdx.x; i < K1_BGRP * QQ; i += blockDim.x)
        sq[i / QQ][i % QQ] = query[(b0 + i / QQ) * QQ + (i % QQ)];
    __syncthreads();

    float acc0 = 0.f, acc1 = 0.f, acc2 = 0.f, acc3 = 0.f;
#pragma unroll 8
    for (int q = 0; q < QQ; q++) {
        float w = W[q * HH + h];
        acc0 = fmaf(w, sq[0][q], acc0);
        acc1 = fmaf(w, sq[1][q], acc1);
        acc2 = fmaf(w, sq[2][q], acc2);
        acc3 = fmaf(w, sq[3][q], acc3);
    }
    g_v[(b0 + 0) * HH + h] = acc0;
    g_v[(b0 + 1) * HH + h] = acc1;
    g_v[(b0 + 2) * HH + h] = acc2;
    g_v[(b0 + 3) * HH + h] = acc3;
}

// ---------------------------------------------------------------------------
// Kernel 2: flash pass over one (chunk, batch). 8 warps, warp-per-row strided.
// Each lane owns 16 h-positions (4 x float4, stride-32 coalesced), ctx in regs.
// Online softmax with rare-rescale branch (warp-uniform after reduce).
// ---------------------------------------------------------------------------
__device__ __forceinline__ float dot4(float4 a, float4 b) {
    return a.x * b.x + a.y * b.y + a.z * b.z + a.w * b.w;
}

__global__ __launch_bounds__(256) void k2_flash(const float* __restrict__ enc,
                                                const int* __restrict__ tgt_raw) {
    const int b = blockIdx.y;
    const int c = blockIdx.x;
    const int tid = threadIdx.x, w = tid >> 5, lane = tid & 31;

    __shared__ int s_is64;
    if (tid == 0) s_is64 = detect_is64(tgt_raw);
    __syncthreads();

    const int L = load_len(tgt_raw, b, s_is64);  // valid rows: t in [0, L)
    const int t0 = c * CHUNK;
    if (t0 >= L) {                               // entirely masked chunk
        if (tid == 0) g_ps[b * NCHUNK + c] = 0.f;
        return;
    }
    const int tend = min(t0 + CHUNK, L);

    // v[b] resident in registers for the whole chunk
    const float4* v4 = (const float4*)(g_v + b * HH);
    const float4 va = v4[lane], vb = v4[lane + 32], vc = v4[lane + 64], vd = v4[lane + 96];

    float m = -INFINITY, s = 0.f;
    float4 c0 = make_float4(0.f, 0.f, 0.f, 0.f), c1 = c0, c2 = c0, c3 = c0;

    const float4* ebase = (const float4*)(enc + (size_t)b * TT * HH);

    int t = t0 + w;
    float4 e0 = make_float4(0.f, 0.f, 0.f, 0.f), e1 = e0, e2 = e0, e3 = e0;
    if (t < tend) {
        const float4* r = ebase + (size_t)t * (HH / 4);
        e0 = r[lane]; e1 = r[lane + 32]; e2 = r[lane + 64]; e3 = r[lane + 96];
    }
    for (; t < tend; t += 8) {
        // prefetch next row (hide DRAM latency behind this row's math)
        float4 n0 = e0, n1 = e1, n2 = e2, n3 = e3;
        const int tn = t + 8;
        if (tn < tend) {
            const float4* r = ebase + (size_t)tn * (HH / 4);
            n0 = r[lane]; n1 = r[lane + 32]; n2 = r[lane + 64]; n3 = r[lane + 96];
        }
        // energy = enc_row . v   (16 FMA + 5 shfl)
        float d = dot4(e0, va) + dot4(e1, vb) + dot4(e2, vc) + dot4(e3, vd);
        d += __shfl_xor_sync(0xFFFFFFFFu, d, 16);
        d += __shfl_xor_sync(0xFFFFFFFFu, d, 8);
        d += __shfl_xor_sync(0xFFFFFFFFu, d, 4);
        d += __shfl_xor_sync(0xFFFFFFFFu, d, 2);
        d += __shfl_xor_sync(0xFFFFFFFFu, d, 1);

        if (d > m) {                      // new max (rare): rescale, p = 1
            const float alpha = __expf(m - d);   // exp(-inf)=0 handles first row
            m = d;
            s = s * alpha + 1.f;
            c0.x = c0.x * alpha + e0.x; c0.y = c0.y * alpha + e0.y;
            c0.z = c0.z * alpha + e0.z; c0.w = c0.w * alpha + e0.w;
            c1.x = c1.x * alpha + e1.x; c1.y = c1.y * alpha + e1.y;
            c1.z = c1.z * alpha + e1.z; c1.w = c1.w * alpha + e1.w;
            c2.x = c2.x * alpha + e2.x; c2.y = c2.y * alpha + e2.y;
            c2.z = c2.z * alpha + e2.z; c2.w = c2.w * alpha + e2.w;
            c3.x = c3.x * alpha + e3.x; c3.y = c3.y * alpha + e3.y;
            c3.z = c3.z * alpha + e3.z; c3.w = c3.w * alpha + e3.w;
        } else {                          // common path: 1 exp + 16 FMA
            const float p = __expf(d - m);
            s += p;
            c0.x = fmaf(p, e0.x, c0.x); c0.y = fmaf(p, e0.y, c0.y);
            c0.z = fmaf(p, e0.z, c0.z); c0.w = fmaf(p, e0.w, c0.w);
            c1.x = fmaf(p, e1.x, c1.x); c1.y = fmaf(p, e1.y, c1.y);
            c1.z = fmaf(p, e1.z, c1.z); c1.w = fmaf(p, e1.w, c1.w);
            c2.x = fmaf(p, e2.x, c2.x); c2.y = fmaf(p, e2.y, c2.y);
            c2.z = fmaf(p, e2.z, c2.z); c2.w = fmaf(p, e2.w, c2.w);
            c3.x = fmaf(p, e3.x, c3.x); c3.y = fmaf(p, e3.y, c3.y);
            c3.z = fmaf(p, e3.z, c3.z); c3.w = fmaf(p, e3.w, c3.w);
        }
        e0 = n0; e1 = n1; e2 = n2; e3 = n3;
    }

    // ---- combine 8 warps inside the block ----
    __shared__ float sM[8], sS[8];
    __shared__ __align__(16) float sctx[8][HH];   // 16 KB
    float4* sc4 = (float4*)sctx[w];
    sc4[lane] = c0; sc4[lane + 32] = c1; sc4[lane + 64] = c2; sc4[lane + 96] = c3;
    if (lane == 0) { sM[w] = m; sS[w] = s; }
    __syncthreads();

    float M = -INFINITY;
#pragma unroll
    for (int i = 0; i < 8; i++) if (sS[i] > 0.f) M = fmaxf(M, sM[i]);
    float S = 0.f, f[8];
#pragma unroll
    for (int i = 0; i < 8; i++) {
        f[i] = (sS[i] > 0.f) ? __expf(sM[i] - M) : 0.f;
        S += sS[i] * f[i];
    }
    const int base = (b * NCHUNK + c) * HH;
    for (int h = tid; h < HH; h += 256) {
        float a = 0.f;
#pragma unroll
        for (int i = 0; i < 8; i++) a = fmaf(sctx[i][h], f[i], a);
        g_pctx[base + h] = a;
    }
    if (tid == 0) { g_pm[b * NCHUNK + c] = M; g_ps[b * NCHUNK + c] = S; }
}

// ---------------------------------------------------------------------------
// Kernel 3: combine the NCHUNK split-softmax partials per batch.
// ---------------------------------------------------------------------------
__global__ void k3_combine(float* __restrict__ out) {
    const int b = blockIdx.x, h = threadIdx.x;   // 512 threads
    float M = -INFINITY;
#pragma unroll
    for (int c = 0; c < NCHUNK; c++) {
        const float s = g_ps[b * NCHUNK + c];
        if (s > 0.f) M = fmaxf(M, g_pm[b * NCHUNK + c]);
    }
    float S = 0.f, acc = 0.f;
#pragma unroll
    for (int c = 0; c < NCHUNK; c++) {
        const float s = g_ps[b * NCHUNK + c];
        if (s > 0.f) {
            const float fct = __expf(g_pm[b * NCHUNK + c] - M);
            S += s * fct;
            acc = fmaf(g_pctx[(b * NCHUNK + c) * HH + h], fct, acc);
        }
    }
    out[b * HH + h] = acc / S;
}

// ---------------------------------------------------------------------------
extern "C" void kernel_launch(void* const* d_in, const int* in_sizes, int n_in,
                              void* d_out, int out_size) {
    // Defensive remap by element count (all sizes unique):
    // query 32768, enc 67108864, W 262144, bias 512, tgt 64
    const float* query = nullptr;
    const float* enc   = nullptr;
    const float* W     = nullptr;
    const int*   tgt   = nullptr;   // dtype (i32 vs i64) detected on device
    for (int i = 0; i < n_in; i++) {
        switch (in_sizes[i]) {
            case BB * QQ:               query = (const float*)d_in[i]; break;
            case BB * TT * HH:          enc   = (const float*)d_in[i]; break;
            case QQ * HH:               W     = (const float*)d_in[i]; break;
            case BB:                    tgt   = (const int*)d_in[i]; break;
            default: break;             // bias (512) unused: softmax-shift invariant
        }
    }

    k1_proj<<<dim3(HH / K1_HTILE, BB / K1_BGRP), K1_HTILE>>>(query, W);
    k2_flash<<<dim3(NCHUNK, BB), 256>>>(enc, tgt);
    k3_combine<<<BB, HH>>>((float*)d_out);
}

// round 3
// speedup vs baseline: 1.9079x; 1.9079x over previous
#include <cuda_runtime.h>
#include <math.h>

#define BB 64
#define TT 2048
#define HH 512
#define QQ 512
#define NCHUNK 16
#define CHUNK (TT / NCHUNK)   // 128 rows per chunk
#define QSPLIT 8
#define QSEG (QQ / QSPLIT)    // 64

// Scratch (allocation-free rule: __device__ globals)
__device__ __align__(16) float g_vp[QSPLIT * BB * HH];   // partial v, 8 MB
__device__ float g_pm[BB * NCHUNK];                      // per-chunk running max
__device__ float g_ps[BB * NCHUNK];                      // per-chunk exp-sum
__device__ __align__(16) float g_pctx[BB * NCHUNK * HH]; // per-chunk weighted ctx (2 MB)

// ---------------------------------------------------------------------------
// tgt_index dtype detection (int64 vs int32), as in R1 — verified working.
// ---------------------------------------------------------------------------
__device__ __forceinline__ int detect_is64(const int* __restrict__ tgt_raw) {
    int odd_or = 0;
#pragma unroll
    for (int i = 1; i < 2 * BB; i += 2) odd_or |= tgt_raw[i];
    return odd_or == 0;
}
__device__ __forceinline__ int load_len(const int* __restrict__ tgt_raw, int b, int is64) {
    return (is64 ? tgt_raw[2 * b] : tgt_raw[b]) + 1;
}

// ---------------------------------------------------------------------------
// Kernel 1: K-split partial matvec. vp[z][b,h] = sum_{q in seg z} q[b,q]*W[q,h]
// grid (QSPLIT, BB/4) = 128 blocks, 128 threads. Thread owns 4 h (float4),
// 4 batches -> 16 independent accumulators; 64 coalesced float4 W loads.
// ---------------------------------------------------------------------------
#define K1_BGRP 4

__global__ __launch_bounds__(128) void k1_proj(const float* __restrict__ query,
                                               const float* __restrict__ W) {
    const int qz = blockIdx.x;
    const int b0 = blockIdx.y * K1_BGRP;
    const int tid = threadIdx.x;          // h4 index: covers h = 4*tid .. 4*tid+3

    __shared__ float sq[K1_BGRP][QSEG];
    for (int i = tid; i < K1_BGRP * QSEG; i += 128)
        sq[i / QSEG][i % QSEG] = query[(b0 + i / QSEG) * QQ + qz * QSEG + (i % QSEG)];
    __syncthreads();

    const float4* W4 = (const float4*)W + (size_t)qz * QSEG * (HH / 4) + tid;
    float4 a0 = make_float4(0.f, 0.f, 0.f, 0.f), a1 = a0, a2 = a0, a3 = a0;

#pragma unroll 16
    for (int q = 0; q < QSEG; q++) {
        const float4 w = W4[q * (HH / 4)];
        const float q0 = sq[0][q], q1 = sq[1][q], q2 = sq[2][q], q3 = sq[3][q];
        a0.x = fmaf(w.x, q0, a0.x); a0.y = fmaf(w.y, q0, a0.y);
        a0.z = fmaf(w.z, q0, a0.z); a0.w = fmaf(w.w, q0, a0.w);
        a1.x = fmaf(w.x, q1, a1.x); a1.y = fmaf(w.y, q1, a1.y);
        a1.z = fmaf(w.z, q1, a1.z); a1.w = fmaf(w.w, q1, a1.w);
        a2.x = fmaf(w.x, q2, a2.x); a2.y = fmaf(w.y, q2, a2.y);
        a2.z = fmaf(w.z, q2, a2.z); a2.w = fmaf(w.w, q2, a2.w);
        a3.x = fmaf(w.x, q3, a3.x); a3.y = fmaf(w.y, q3, a3.y);
        a3.z = fmaf(w.z, q3, a3.z); a3.w = fmaf(w.w, q3, a3.w);
    }

    float4* vp = (float4*)g_vp + (size_t)qz * BB * (HH / 4);
    vp[(b0 + 0) * (HH / 4) + tid] = a0;
    vp[(b0 + 1) * (HH / 4) + tid] = a1;
    vp[(b0 + 2) * (HH / 4) + tid] = a2;
    vp[(b0 + 3) * (HH / 4) + tid] = a3;
}

// ---------------------------------------------------------------------------
// Kernel 2: flash pass over one (chunk, batch). 8 warps, warp-per-row strided.
// v[b] reduced from the 8 K-split partials at block start (L2-hit loads).
// ---------------------------------------------------------------------------
__device__ __forceinline__ float dot4(float4 a, float4 b) {
    return a.x * b.x + a.y * b.y + a.z * b.z + a.w * b.w;
}

__global__ __launch_bounds__(256) void k2_flash(const float* __restrict__ enc,
                                                const int* __restrict__ tgt_raw) {
    const int b = blockIdx.y;
    const int c = blockIdx.x;
    const int tid = threadIdx.x, w = tid >> 5, lane = tid & 31;

    __shared__ int s_is64;
    if (tid == 0) s_is64 = detect_is64(tgt_raw);
    __syncthreads();

    const int L = load_len(tgt_raw, b, s_is64);  // valid rows: t in [0, L)
    const int t0 = c * CHUNK;
    if (t0 >= L) {                               // entirely masked chunk
        if (tid == 0) g_ps[b * NCHUNK + c] = 0.f;
        return;
    }
    const int tend = min(t0 + CHUNK, L);

    // v[b] = sum of QSPLIT partials, resident in registers for the whole chunk
    float4 va = make_float4(0.f, 0.f, 0.f, 0.f), vb = va, vc = va, vd = va;
#pragma unroll
    for (int z = 0; z < QSPLIT; z++) {
        const float4* vp = (const float4*)g_vp + ((size_t)z * BB + b) * (HH / 4);
        const float4 p0 = vp[lane], p1 = vp[lane + 32], p2 = vp[lane + 64], p3 = vp[lane + 96];
        va.x += p0.x; va.y += p0.y; va.z += p0.z; va.w += p0.w;
        vb.x += p1.x; vb.y += p1.y; vb.z += p1.z; vb.w += p1.w;
        vc.x += p2.x; vc.y += p2.y; vc.z += p2.z; vc.w += p2.w;
        vd.x += p3.x; vd.y += p3.y; vd.z += p3.z; vd.w += p3.w;
    }

    float m = -INFINITY, s = 0.f;
    float4 c0 = make_float4(0.f, 0.f, 0.f, 0.f), c1 = c0, c2 = c0, c3 = c0;

    const float4* ebase = (const float4*)(enc + (size_t)b * TT * HH);

    int t = t0 + w;
    float4 e0 = make_float4(0.f, 0.f, 0.f, 0.f), e1 = e0, e2 = e0, e3 = e0;
    if (t < tend) {
        const float4* r = ebase + (size_t)t * (HH / 4);
        e0 = r[lane]; e1 = r[lane + 32]; e2 = r[lane + 64]; e3 = r[lane + 96];
    }
    for (; t < tend; t += 8) {
        // prefetch next row (hide DRAM latency behind this row's math)
        float4 n0 = e0, n1 = e1, n2 = e2, n3 = e3;
        const int tn = t + 8;
        if (tn < tend) {
            const float4* r = ebase + (size_t)tn * (HH / 4);
            n0 = r[lane]; n1 = r[lane + 32]; n2 = r[lane + 64]; n3 = r[lane + 96];
        }
        // energy = enc_row . v   (16 FMA + 5 shfl)
        float d = dot4(e0, va) + dot4(e1, vb) + dot4(e2, vc) + dot4(e3, vd);
        d += __shfl_xor_sync(0xFFFFFFFFu, d, 16);
        d += __shfl_xor_sync(0xFFFFFFFFu, d, 8);
        d += __shfl_xor_sync(0xFFFFFFFFu, d, 4);
        d += __shfl_xor_sync(0xFFFFFFFFu, d, 2);
        d += __shfl_xor_sync(0xFFFFFFFFu, d, 1);

        if (d > m) {                      // new max (rare): rescale, p = 1
            const float alpha = __expf(m - d);   // exp(-inf)=0 handles first row
            m = d;
            s = s * alpha + 1.f;
            c0.x = c0.x * alpha + e0.x; c0.y = c0.y * alpha + e0.y;
            c0.z = c0.z * alpha + e0.z; c0.w = c0.w * alpha + e0.w;
            c1.x = c1.x * alpha + e1.x; c1.y = c1.y * alpha + e1.y;
            c1.z = c1.z * alpha + e1.z; c1.w = c1.w * alpha + e1.w;
            c2.x = c2.x * alpha + e2.x; c2.y = c2.y * alpha + e2.y;
            c2.z = c2.z * alpha + e2.z; c2.w = c2.w * alpha + e2.w;
            c3.x = c3.x * alpha + e3.x; c3.y = c3.y * alpha + e3.y;
            c3.z = c3.z * alpha + e3.z; c3.w = c3.w * alpha + e3.w;
        } else {                          // common path: 1 exp + 16 FMA
            const float p = __expf(d - m);
            s += p;
            c0.x = fmaf(p, e0.x, c0.x); c0.y = fmaf(p, e0.y, c0.y);
            c0.z = fmaf(p, e0.z, c0.z); c0.w = fmaf(p, e0.w, c0.w);
            c1.x = fmaf(p, e1.x, c1.x); c1.y = fmaf(p, e1.y, c1.y);
            c1.z = fmaf(p, e1.z, c1.z); c1.w = fmaf(p, e1.w, c1.w);
            c2.x = fmaf(p, e2.x, c2.x); c2.y = fmaf(p, e2.y, c2.y);
            c2.z = fmaf(p, e2.z, c2.z); c2.w = fmaf(p, e2.w, c2.w);
            c3.x = fmaf(p, e3.x, c3.x); c3.y = fmaf(p, e3.y, c3.y);
            c3.z = fmaf(p, e3.z, c3.z); c3.w = fmaf(p, e3.w, c3.w);
        }
        e0 = n0; e1 = n1; e2 = n2; e3 = n3;
    }

    // ---- combine 8 warps inside the block ----
    __shared__ float sM[8], sS[8];
    __shared__ __align__(16) float sctx[8][HH];   // 16 KB
    float4* sc4 = (float4*)sctx[w];
    sc4[lane] = c0; sc4[lane + 32] = c1; sc4[lane + 64] = c2; sc4[lane + 96] = c3;
    if (lane == 0) { sM[w] = m; sS[w] = s; }
    __syncthreads();

    float M = -INFINITY;
#pragma unroll
    for (int i = 0; i < 8; i++) if (sS[i] > 0.f) M = fmaxf(M, sM[i]);
    float S = 0.f, f[8];
#pragma unroll
    for (int i = 0; i < 8; i++) {
        f[i] = (sS[i] > 0.f) ? __expf(sM[i] - M) : 0.f;
        S += sS[i] * f[i];
    }
    const int base = (b * NCHUNK + c) * HH;
    for (int h = tid; h < HH; h += 256) {
        float a = 0.f;
#pragma unroll
        for (int i = 0; i < 8; i++) a = fmaf(sctx[i][h], f[i], a);
        g_pctx[base + h] = a;
    }
    if (tid == 0) { g_pm[b * NCHUNK + c] = M; g_ps[b * NCHUNK + c] = S; }
}

// ---------------------------------------------------------------------------
// Kernel 3: combine the NCHUNK split-softmax partials per batch.
// ---------------------------------------------------------------------------
__global__ void k3_combine(float* __restrict__ out) {
    const int b = blockIdx.x, h = threadIdx.x;   // 512 threads
    float M = -INFINITY;
#pragma unroll
    for (int c = 0; c < NCHUNK; c++) {
        const float s = g_ps[b * NCHUNK + c];
        if (s > 0.f) M = fmaxf(M, g_pm[b * NCHUNK + c]);
    }
    float S = 0.f, acc = 0.f;
#pragma unroll
    for (int c = 0; c < NCHUNK; c++) {
        const float s = g_ps[b * NCHUNK + c];
        if (s > 0.f) {
            const float fct = __expf(g_pm[b * NCHUNK + c] - M);
            S += s * fct;
            acc = fmaf(g_pctx[(b * NCHUNK + c) * HH + h], fct, acc);
        }
    }
    out[b * HH + h] = acc / S;
}

// ---------------------------------------------------------------------------
extern "C" void kernel_launch(void* const* d_in, const int* in_sizes, int n_in,
                              void* d_out, int out_size) {
    const float* query = nullptr;
    const float* enc   = nullptr;
    const float* W     = nullptr;
    const int*   tgt   = nullptr;   // dtype (i32 vs i64) detected on device
    for (int i = 0; i < n_in; i++) {
        switch (in_sizes[i]) {
            case BB * QQ:               query = (const float*)d_in[i]; break;
            case BB * TT * HH:          enc   = (const float*)d_in[i]; break;
            case QQ * HH:               W     = (const float*)d_in[i]; break;
            case BB:                    tgt   = (const int*)d_in[i]; break;
            default: break;             // bias (512) unused: softmax-shift invariant
        }
    }

    k1_proj<<<dim3(QSPLIT, BB / K1_BGRP), 128>>>(query, W);
    k2_flash<<<dim3(NCHUNK, BB), 256>>>(enc, tgt);
    k3_combine<<<BB, HH>>>((float*)d_out);
}